// round 1
// baseline (speedup 1.0000x reference)
#include <cuda_runtime.h>
#include <math.h>

#define NB 16
#define NT 50
#define NA 3
#define NG 76
#define PLANE (NG*NG)            // 5776
#define NC 85                    // 5 + 80 classes
#define CH (NA*NC)               // 255
#define CELL_WORDS ((PLANE + 31) / 32)            // 181
#define MASK_BITS (NB*NA*PLANE)                   // 277248
#define MASK_WORDS ((MASK_BITS + 31) / 32)        // 8664
#define NOOBJ_SPLIT 4
#define CHUNK (PLANE / NOOBJ_SPLIT)               // 1444

// ---------------- device scratch (no allocations allowed) ----------------
__device__ unsigned int g_cell_zero[CELL_WORDS];
__device__ unsigned int g_maskbits[MASK_WORDS];
__device__ float g_sx, g_sy, g_sw, g_sh, g_sobj;
__device__ float g_nm;        // sum(mask) = #distinct positions
__device__ float g_snoobj;
__device__ int   g_nnoobj;
__device__ int   g_done;

__device__ __forceinline__ float block_reduce(float v, float* sh) {
    int lane = threadIdx.x & 31, wid = threadIdx.x >> 5;
    #pragma unroll
    for (int o = 16; o; o >>= 1) v += __shfl_down_sync(0xffffffffu, v, o);
    if (lane == 0) sh[wid] = v;
    __syncthreads();
    int nw = (blockDim.x + 31) >> 5;
    v = (threadIdx.x < nw) ? sh[threadIdx.x] : 0.f;
    if (wid == 0) {
        #pragma unroll
        for (int o = 16; o; o >>= 1) v += __shfl_down_sync(0xffffffffu, v, o);
    }
    __syncthreads();
    return v;  // valid in thread 0
}

// ---------------- K1: build targets + sparse loss terms ----------------
__global__ __launch_bounds__(1024, 1)
void k_build(const float* __restrict__ sample,
             const float* __restrict__ targets,
             const float* __restrict__ anchors)
{
    __shared__ int   s_key[NB*NT];
    __shared__ float s_gx[NB*NT], s_gy[NB*NT], s_gw[NB*NT], s_gh[NB*NT];
    __shared__ int   s_bn[NB*NT];
    __shared__ float s_red[32];

    int tid = threadIdx.x;

    // zero scratch
    for (int i = tid; i < CELL_WORDS; i += blockDim.x) g_cell_zero[i] = 0u;
    for (int i = tid; i < MASK_WORDS; i += blockDim.x) g_maskbits[i] = 0u;
    if (tid == 0) { g_snoobj = 0.f; g_nnoobj = 0; g_done = 0; }
    __syncthreads();

    const float stride = 608.0f / (float)NG;   // 8
    float awS[NA], ahS[NA];
    #pragma unroll
    for (int a = 0; a < NA; a++) {
        awS[a] = anchors[2*a]   / stride;
        ahS[a] = anchors[2*a+1] / stride;
    }

    if (tid < NB*NT) {
        int b = tid / NT;
        const float* tg = targets + (size_t)tid * 5;
        const float* t0 = targets + (size_t)(b*NT) * 5;
        float s5 = tg[0] + tg[1] + tg[2] + tg[3] + tg[4];
        bool mm = s5 > 0.f;
        float cx = mm ? tg[1] : t0[1];
        float cy = mm ? tg[2] : t0[2];
        float cw = mm ? tg[3] : t0[3];
        float chh = mm ? tg[4] : t0[4];
        float gx = cx * NG, gy = cy * NG, gw = cw * NG, gh = chh * NG;
        int gi = (int)gx, gj = (int)gy;

        float best = -1e30f; int bn = 0; bool ign = false;
        #pragma unroll
        for (int a = 0; a < NA; a++) {
            float iw = fminf(gw, awS[a]) + 1.f;
            float ih = fminf(gh, ahS[a]) + 1.f;
            float inter = fmaxf(iw, 0.f) * fmaxf(ih, 0.f);
            float denom = (gw + 1.f) * (gh + 1.f) + (awS[a] + 1.f) * (ahS[a] + 1.f)
                          - inter + 1e-12f;
            float iou = inter / denom;
            if (iou > 0.5f) ign = true;
            if (iou > best) { best = iou; bn = a; }   // first-max wins ties
        }

        int cell = gj * NG + gi;
        if (ign) atomicOr(&g_cell_zero[cell >> 5], 1u << (cell & 31));
        int key = (b * NA + bn) * PLANE + cell;
        atomicOr(&g_maskbits[key >> 5], 1u << (key & 31));

        s_key[tid] = key;
        s_gx[tid] = gx; s_gy[tid] = gy; s_gw[tid] = gw; s_gh[tid] = gh;
        s_bn[tid] = bn;
    }
    __syncthreads();

    float sx = 0.f, sy = 0.f, sw = 0.f, sh = 0.f, sobj = 0.f, nm = 0.f;
    if (tid < NB*NT) {
        int b = tid / NT, t = tid % NT;
        bool winner = true;
        int base = b * NT;
        int mykey = s_key[tid];
        for (int t2 = t + 1; t2 < NT; t2++)
            if (s_key[base + t2] == mykey) { winner = false; break; }

        if (winner) {
            float gx = s_gx[tid], gy = s_gy[tid], gw = s_gw[tid], gh = s_gh[tid];
            int bn = s_bn[tid];
            int gi = (int)gx, gj = (int)gy;
            size_t off = ((size_t)(b * CH + bn * NC)) * PLANE + (size_t)(gj * NG + gi);
            float p0 = sample[off];
            float p1 = sample[off + 1 * PLANE];
            float p2 = sample[off + 2 * PLANE];
            float p3 = sample[off + 3 * PLANE];
            float p4 = sample[off + 4 * PLANE];

            float x  = 1.f / (1.f + expf(-p0));
            float y  = 1.f / (1.f + expf(-p1));
            float pc = 1.f / (1.f + expf(-p4));
            float tx = gx - (float)gi;
            float ty = gy - (float)gj;
            float tw = logf(gw / awS[bn] + 1e-16f);
            float th = logf(gh / ahS[bn] + 1e-16f);

            float dx = x - tx, dy = y - ty, dw = p2 - tw, dh = p3 - th;
            sx = dx * dx; sy = dy * dy; sw = dw * dw; sh = dh * dh;
            sobj = -logf(pc + 1e-12f);
            nm = 1.f;
        }
    }

    float r;
    r = block_reduce(sx, s_red);   if (tid == 0) g_sx = r;
    r = block_reduce(sy, s_red);   if (tid == 0) g_sy = r;
    r = block_reduce(sw, s_red);   if (tid == 0) g_sw = r;
    r = block_reduce(sh, s_red);   if (tid == 0) g_sh = r;
    r = block_reduce(sobj, s_red); if (tid == 0) g_sobj = r;
    r = block_reduce(nm, s_red);   if (tid == 0) g_nm = r;
}

// ---------------- K2: dense noobj BCE + final combine ----------------
__global__ __launch_bounds__(256, 8)
void k_noobj(const float* __restrict__ sample, float* __restrict__ out)
{
    __shared__ float s_red[32];
    int blk = blockIdx.x;                 // 0 .. NB*NA*NOOBJ_SPLIT-1
    int ba = blk / NOOBJ_SPLIT;           // (b, a) plane id
    int chunk = blk % NOOBJ_SPLIT;
    int b = ba / NA, a = ba % NA;

    const float* conf = sample + ((size_t)(b * CH + a * NC + 4)) * PLANE;

    float s = 0.f; int cnt = 0;
    int p0 = chunk * CHUNK;
    for (int p = p0 + threadIdx.x; p < p0 + CHUNK; p += blockDim.x) {
        unsigned cz = (g_cell_zero[p >> 5] >> (p & 31)) & 1u;
        int bit = ba * PLANE + p;
        unsigned mk = (g_maskbits[bit >> 5] >> (bit & 31)) & 1u;
        if (!(cz | mk)) {
            float v = conf[p];
            float pc = 1.f / (1.f + expf(-v));
            s += -logf(1.f - pc + 1e-12f);
            cnt++;
        }
    }

    float rs = block_reduce(s, s_red);
    float rc = block_reduce((float)cnt, s_red);
    if (threadIdx.x == 0) {
        atomicAdd(&g_snoobj, rs);
        atomicAdd(&g_nnoobj, (int)(rc + 0.5f));
        __threadfence();
        if (atomicAdd(&g_done, 1) == gridDim.x - 1) {
            float nm = fmaxf(g_nm, 1.f);
            float lx = 2.0f * g_sx / nm;
            float ly = 2.0f * g_sy / nm;
            float lw = 1.6f * g_sw / nm;
            float lh = 1.6f * g_sh / nm;
            float lobj = 1.0f * g_sobj / nm;
            float lnoobj = 0.5f * g_snoobj / fmaxf((float)g_nnoobj, 1.f);
            out[0] = lx + ly + lw + lh + lnoobj + lobj;
            out[1] = lx; out[2] = ly; out[3] = lw; out[4] = lh;
            out[5] = lobj; out[6] = lnoobj;
        }
    }
}

extern "C" void kernel_launch(void* const* d_in, const int* in_sizes, int n_in,
                              void* d_out, int out_size)
{
    const float* sample  = (const float*)d_in[0];
    const float* targets = (const float*)d_in[1];
    const float* anchors = (const float*)d_in[2];
    float* out = (float*)d_out;

    k_build<<<1, 1024>>>(sample, targets, anchors);
    k_noobj<<<NB * NA * NOOBJ_SPLIT, 256>>>(sample, out);
}

// round 2
// speedup vs baseline: 1.9458x; 1.9458x over previous
#include <cuda_runtime.h>
#include <math.h>

#define NB 16
#define NT 50
#define NA 3
#define NG 76
#define PLANE (NG*NG)            // 5776
#define NC 85
#define CH (NA*NC)               // 255
#define NBT (NB*NT)              // 800
#define CELL_WORDS ((PLANE + 31) / 32)   // 181
#define NOOBJ_SPLIT 4
#define CHUNK (PLANE / NOOBJ_SPLIT)      // 1444
#define CHUNK4 (CHUNK / 4)               // 361
#define TOTAL_CONF (NB*NA*PLANE)         // 277248
#define K2_BLOCKS (NB*NA*NOOBJ_SPLIT)    // 192

// ---------------- device scratch ----------------
__device__ float g_sx, g_sy, g_sw, g_sh, g_sobj;
__device__ float g_nm;          // #distinct mask positions
__device__ float g_mcs;         // mask-correction softplus sum
__device__ float g_mcc;         // mask-correction count
__device__ int   g_nz;          // #distinct ignore cells
__device__ int   g_zlist[832];  // ignore cell indices
__device__ float g_snoobj;      // dense softplus sum minus zero-cell corrections
__device__ int   g_done;

__device__ __forceinline__ float softplus_f(float v) {
    // ln(1+e^v) == -ln(1 - sigmoid(v))  (eps 1e-12 negligible for |v| < 27)
    float a = fabsf(v);
    return fmaxf(v, 0.f) + __logf(1.f + __expf(-a));
}

__device__ __forceinline__ float block_reduce(float v, float* sh) {
    int lane = threadIdx.x & 31, wid = threadIdx.x >> 5;
    #pragma unroll
    for (int o = 16; o; o >>= 1) v += __shfl_down_sync(0xffffffffu, v, o);
    if (lane == 0) sh[wid] = v;
    __syncthreads();
    int nw = (blockDim.x + 31) >> 5;
    v = (threadIdx.x < nw) ? sh[threadIdx.x] : 0.f;
    if (wid == 0) {
        #pragma unroll
        for (int o = 16; o; o >>= 1) v += __shfl_down_sync(0xffffffffu, v, o);
    }
    __syncthreads();
    return v;  // valid in thread 0
}

// ---------------- K1: build targets, sparse terms, ignore list ----------------
__global__ __launch_bounds__(1024, 1)
void k_build(const float* __restrict__ sample,
             const float* __restrict__ targets,
             const float* __restrict__ anchors)
{
    __shared__ int      s_key[NBT];
    __shared__ float    s_gx[NBT], s_gy[NBT], s_gw[NBT], s_gh[NBT];
    __shared__ unsigned s_zero[CELL_WORDS];
    __shared__ float    s_red[32];
    __shared__ int      s_nz;

    int tid = threadIdx.x;
    if (tid < CELL_WORDS) s_zero[tid] = 0u;
    if (tid == 0) { s_nz = 0; g_done = 0; g_snoobj = 0.f; }

    const float stride = 608.0f / (float)NG;   // 8
    float awS[NA], ahS[NA];
    #pragma unroll
    for (int a = 0; a < NA; a++) {
        awS[a] = anchors[2*a]   / stride;
        ahS[a] = anchors[2*a+1] / stride;
    }
    __syncthreads();

    if (tid < NBT) {
        int b = tid / NT;
        const float* tg = targets + (size_t)tid * 5;
        const float* t0 = targets + (size_t)(b*NT) * 5;
        float s5 = tg[0] + tg[1] + tg[2] + tg[3] + tg[4];
        bool mm = s5 > 0.f;
        float gx = (mm ? tg[1] : t0[1]) * NG;
        float gy = (mm ? tg[2] : t0[2]) * NG;
        float gw = (mm ? tg[3] : t0[3]) * NG;
        float gh = (mm ? tg[4] : t0[4]) * NG;
        int gi = (int)gx, gj = (int)gy;

        float best = -1e30f; int bn = 0; bool ign = false;
        #pragma unroll
        for (int a = 0; a < NA; a++) {
            float iw = fminf(gw, awS[a]) + 1.f;
            float ih = fminf(gh, ahS[a]) + 1.f;
            float inter = fmaxf(iw, 0.f) * fmaxf(ih, 0.f);
            float denom = (gw + 1.f) * (gh + 1.f) + (awS[a] + 1.f) * (ahS[a] + 1.f)
                          - inter + 1e-12f;
            float iou = inter / denom;
            if (iou > 0.5f) ign = true;
            if (iou > best) { best = iou; bn = a; }   // first-max wins ties
        }

        int cell = gj * NG + gi;
        if (ign) atomicOr(&s_zero[cell >> 5], 1u << (cell & 31));
        s_key[tid] = (b * NA + bn) * PLANE + cell;
        s_gx[tid] = gx; s_gy[tid] = gy; s_gw[tid] = gw; s_gh[tid] = gh;
    }
    __syncthreads();

    // compact ignore-cell list
    if (tid < CELL_WORDS) {
        unsigned w = s_zero[tid];
        int n = __popc(w);
        if (n) {
            int pos = atomicAdd(&s_nz, n);
            while (w) {
                int bit = __ffs(w) - 1; w &= w - 1;
                g_zlist[pos++] = tid * 32 + bit;
            }
        }
    }

    float sx = 0.f, sy = 0.f, sw = 0.f, sh = 0.f, sobj = 0.f, nm = 0.f;
    float mcs = 0.f, mcc = 0.f;
    if (tid < NBT) {
        int b = tid / NT, t = tid % NT;
        int mykey = s_key[tid];
        bool winner = true;
        int base = b * NT;
        for (int t2 = t + 1; t2 < NT; t2++)
            if (s_key[base + t2] == mykey) { winner = false; break; }

        if (winner) {
            float gx = s_gx[tid], gy = s_gy[tid], gw = s_gw[tid], gh = s_gh[tid];
            int cell = mykey % PLANE;
            int bn   = (mykey / PLANE) % NA;
            int gi = (int)gx, gj = (int)gy;
            size_t off = ((size_t)(b * CH + bn * NC)) * PLANE + (size_t)cell;
            float p0 = sample[off];
            float p1 = sample[off + 1 * PLANE];
            float p2 = sample[off + 2 * PLANE];
            float p3 = sample[off + 3 * PLANE];
            float p4 = sample[off + 4 * PLANE];

            float x  = 1.f / (1.f + __expf(-p0));
            float y  = 1.f / (1.f + __expf(-p1));
            float pc = 1.f / (1.f + __expf(-p4));
            float tx = gx - (float)gi;
            float ty = gy - (float)gj;
            float tw = __logf(gw / awS[bn] + 1e-16f);
            float th = __logf(gh / ahS[bn] + 1e-16f);

            float dx = x - tx, dy = y - ty, dw = p2 - tw, dh = p3 - th;
            sx = dx * dx; sy = dy * dy; sw = dw * dw; sh = dh * dh;
            sobj = -__logf(pc + 1e-12f);
            nm = 1.f;

            // this mask position is excluded from noobj; if its cell isn't in
            // the ignore set, K2's dense sum still contains it -> subtract here
            if (!((s_zero[cell >> 5] >> (cell & 31)) & 1u)) {
                mcs = softplus_f(p4);
                mcc = 1.f;
            }
        }
    }

    float r;
    r = block_reduce(sx, s_red);   if (tid == 0) g_sx = r;
    r = block_reduce(sy, s_red);   if (tid == 0) g_sy = r;
    r = block_reduce(sw, s_red);   if (tid == 0) g_sw = r;
    r = block_reduce(sh, s_red);   if (tid == 0) g_sh = r;
    r = block_reduce(sobj, s_red); if (tid == 0) g_sobj = r;
    r = block_reduce(nm, s_red);   if (tid == 0) g_nm = r;
    r = block_reduce(mcs, s_red);  if (tid == 0) g_mcs = r;
    r = block_reduce(mcc, s_red);  if (tid == 0) { g_mcc = r; g_nz = s_nz; }
}

// ---------------- K2: unconditional dense softplus + corrections + combine ----------------
__global__ __launch_bounds__(256, 8)
void k_noobj(const float* __restrict__ sample, float* __restrict__ out)
{
    __shared__ float s_red[32];
    int ba = blockIdx.x >> 2;                // (b, a) plane id
    int chunk = blockIdx.x & 3;
    int b = ba / NA, a = ba % NA;

    const float* conf = sample + ((size_t)(b * CH + a * NC + 4)) * PLANE;
    int p0 = chunk * CHUNK;

    // dense: 361 float4 per chunk, two rounds, branch-free loads
    const float4* c4 = (const float4*)(conf + p0);
    int i = threadIdx.x;
    float4 v0 = c4[i];
    bool h2 = (i + 256) < CHUNK4;
    float4 v1 = h2 ? c4[i + 256] : make_float4(0.f, 0.f, 0.f, 0.f);

    float s = softplus_f(v0.x) + softplus_f(v0.y) + softplus_f(v0.z) + softplus_f(v0.w);
    if (h2)
        s += softplus_f(v1.x) + softplus_f(v1.y) + softplus_f(v1.z) + softplus_f(v1.w);

    // subtract ignore-cell contributions falling in this chunk
    int nz = g_nz;
    for (int t = threadIdx.x; t < nz; t += 256) {
        int cell = g_zlist[t];
        int p = cell - p0;
        if (p >= 0 && p < CHUNK) s -= softplus_f(conf[cell]);
    }

    float rs = block_reduce(s, s_red);
    if (threadIdx.x == 0) {
        atomicAdd(&g_snoobj, rs);
        __threadfence();
        if (atomicAdd(&g_done, 1) == K2_BLOCKS - 1) {
            float nm = fmaxf(g_nm, 1.f);
            float lx = 2.0f * g_sx / nm;
            float ly = 2.0f * g_sy / nm;
            float lw = 1.6f * g_sw / nm;
            float lh = 1.6f * g_sh / nm;
            float lobj = 1.0f * g_sobj / nm;
            float ncnt = (float)(TOTAL_CONF - 48 * g_nz) - g_mcc;
            float lnoobj = 0.5f * (g_snoobj - g_mcs) / fmaxf(ncnt, 1.f);
            out[0] = lx + ly + lw + lh + lnoobj + lobj;
            out[1] = lx; out[2] = ly; out[3] = lw; out[4] = lh;
            out[5] = lobj; out[6] = lnoobj;
        }
    }
}

extern "C" void kernel_launch(void* const* d_in, const int* in_sizes, int n_in,
                              void* d_out, int out_size)
{
    const float* sample  = (const float*)d_in[0];
    const float* targets = (const float*)d_in[1];
    const float* anchors = (const float*)d_in[2];
    float* out = (float*)d_out;

    k_build<<<1, 1024>>>(sample, targets, anchors);
    k_noobj<<<K2_BLOCKS, 256>>>(sample, out);
}